// round 7
// baseline (speedup 1.0000x reference)
#include <cuda_runtime.h>
#include <cuda_fp16.h>
#include <cstdint>

#define N_TOK 8192
#define DIM   2048
#define NEXP  8

#define BM 128
#define BN 128
#define BK 64                  // fp16 K elems per chunk (128B row)
#define NCH (DIM / BK)         // 32
#define NSTAGE 3

#define PITCH 144              // 128B data + 16B pad -> conflict-free LDSM
#define A_TILE (BM * PITCH)    // 18432
#define B_TILE (BN * PITCH)    // 18432
#define ST_SIZE (A_TILE + B_TILE)        // 36864
#define OFF_TOK  (NSTAGE * ST_SIZE)      // 110592
#define OFF_WT   (OFF_TOK + 512)
#define OFF_SLOT (OFF_WT + 512)
#define SMEM_BYTES (OFF_SLOT + 512)      // 112128 -> 2 CTAs/SM

// ---- scratch ---------------------------------------------------------------
__device__ int   g_count[NEXP];
__device__ int   g_tok[NEXP][N_TOK];
__device__ float g_wt[NEXP][N_TOK];
__device__ int   g_slot[NEXP][N_TOK];
__device__ float g_C[2ull * N_TOK * DIM];
__device__ __align__(16) __half g_Wh[(size_t)NEXP * DIM * DIM];
__device__ __align__(16) __half g_Xh[(size_t)N_TOK * DIM];

// ---- helpers -----------------------------------------------------------------
__device__ __forceinline__ uint32_t smem_u32(const void* p) {
    return (uint32_t)__cvta_generic_to_shared(p);
}
__device__ __forceinline__ void cp16(uint32_t dst, const void* src) {
    asm volatile("cp.async.ca.shared.global [%0], [%1], 16;" :: "r"(dst), "l"(src));
}
__device__ __forceinline__ void cp_commit() {
    asm volatile("cp.async.commit_group;" ::: "memory");
}
template <int N>
__device__ __forceinline__ void cp_wait() {
    asm volatile("cp.async.wait_group %0;" :: "n"(N) : "memory");
}
__device__ __forceinline__ void ldsm4(uint32_t& r0, uint32_t& r1, uint32_t& r2,
                                      uint32_t& r3, uint32_t addr) {
    asm volatile("ldmatrix.sync.aligned.m8n8.x4.shared.b16 {%0,%1,%2,%3}, [%4];"
                 : "=r"(r0), "=r"(r1), "=r"(r2), "=r"(r3) : "r"(addr));
}
__device__ __forceinline__ void mma16816(float* c, const uint32_t* a, const uint32_t* b) {
    asm volatile(
        "mma.sync.aligned.m16n8k16.row.col.f32.f16.f16.f32 "
        "{%0,%1,%2,%3}, {%4,%5,%6,%7}, {%8,%9}, {%0,%1,%2,%3};"
        : "+f"(c[0]), "+f"(c[1]), "+f"(c[2]), "+f"(c[3])
        : "r"(a[0]), "r"(a[1]), "r"(a[2]), "r"(a[3]), "r"(b[0]), "r"(b[1]));
}

// ---- reset -----------------------------------------------------------------
__global__ void reset_kernel() {
    if (threadIdx.x < NEXP) g_count[threadIdx.x] = 0;
}

// ---- fp32 -> fp16 converter ----------------------------------------------------
__global__ void convert_f32_f16(const float* __restrict__ src,
                                __half* __restrict__ dst, size_t n4) {
    size_t i = (size_t)blockIdx.x * blockDim.x + threadIdx.x;
    if (i < n4) {
        float4 v = __ldg(((const float4*)src) + i);
        __half2 a = __floats2half2_rn(v.x, v.y);
        __half2 b = __floats2half2_rn(v.z, v.w);
        ((uint2*)dst)[i] = make_uint2(*(uint32_t*)&a, *(uint32_t*)&b);
    }
}

// ---- gating: 2 tokens per warp -------------------------------------------------
__global__ void gating_kernel(const float* __restrict__ x,
                              const float* __restrict__ Wg,
                              const float* __restrict__ bg) {
    int warp = (blockIdx.x * blockDim.x + threadIdx.x) >> 5;
    int lane = threadIdx.x & 31;
    int t0 = warp * 2;
    if (t0 >= N_TOK) return;

    const float4* xr0 = reinterpret_cast<const float4*>(x + (size_t)t0 * DIM);
    const float4* xr1 = reinterpret_cast<const float4*>(x + (size_t)(t0 + 1) * DIM);
    float acc0[NEXP], acc1[NEXP];
#pragma unroll
    for (int e = 0; e < NEXP; e++) { acc0[e] = 0.f; acc1[e] = 0.f; }

    for (int d4 = lane; d4 < DIM / 4; d4 += 32) {
        float4 xv0 = __ldg(&xr0[d4]);
        float4 xv1 = __ldg(&xr1[d4]);
#pragma unroll
        for (int e = 0; e < NEXP; e++) {
            float4 wv = __ldg(&reinterpret_cast<const float4*>(Wg + (size_t)e * DIM)[d4]);
            acc0[e] += xv0.x * wv.x + xv0.y * wv.y + xv0.z * wv.z + xv0.w * wv.w;
            acc1[e] += xv1.x * wv.x + xv1.y * wv.y + xv1.z * wv.z + xv1.w * wv.w;
        }
    }
#pragma unroll
    for (int e = 0; e < NEXP; e++) {
#pragma unroll
        for (int off = 16; off > 0; off >>= 1) {
            acc0[e] += __shfl_xor_sync(0xffffffffu, acc0[e], off);
            acc1[e] += __shfl_xor_sync(0xffffffffu, acc1[e], off);
        }
    }

    if (lane == 0) {
#pragma unroll
        for (int t = 0; t < 2; t++) {
            float* acc = t ? acc1 : acc0;
            int tok = t0 + t;
            float lg[NEXP];
            float mx = -1e30f;
#pragma unroll
            for (int e = 0; e < NEXP; e++) { lg[e] = acc[e] + bg[e]; mx = fmaxf(mx, lg[e]); }
            float s = 0.f;
#pragma unroll
            for (int e = 0; e < NEXP; e++) { lg[e] = expf(lg[e] - mx); s += lg[e]; }
            float inv = 1.f / s;

            int e0 = 0;
#pragma unroll
            for (int e = 1; e < NEXP; e++) if (lg[e] > lg[e0]) e0 = e;
            int e1 = (e0 == 0) ? 1 : 0;
#pragma unroll
            for (int e = 0; e < NEXP; e++) if (e != e0 && lg[e] > lg[e1]) e1 = e;

            int p0 = atomicAdd(&g_count[e0], 1);
            g_tok[e0][p0] = tok; g_wt[e0][p0] = lg[e0] * inv; g_slot[e0][p0] = 0;
            int p1 = atomicAdd(&g_count[e1], 1);
            g_tok[e1][p1] = tok; g_wt[e1][p1] = lg[e1] * inv; g_slot[e1][p1] = 1;
        }
    }
}

// ---- fp16 mma.sync expert GEMM: R4 loop structure, 128x128 tile, 2 CTAs/SM -----
__global__ __launch_bounds__(256, 2)
void expert_gemm_mma(const float* __restrict__ be) {
    extern __shared__ __align__(128) char smem[];

    const int e  = blockIdx.z;
    const int Me = g_count[e];
    const int m0 = blockIdx.y * BM;
    if (m0 >= Me) return;
    const int n0 = blockIdx.x * BN;

    const int tid  = threadIdx.x;
    const int wid  = tid >> 5;
    const int lane = tid & 31;

    int*   tok_s  = (int*)(smem + OFF_TOK);
    float* w_s    = (float*)(smem + OFF_WT);
    int*   slot_s = (int*)(smem + OFF_SLOT);

    if (tid < BM) {
        int gm = m0 + tid;
        if (gm < Me) {
            tok_s[tid] = g_tok[e][gm]; w_s[tid] = g_wt[e][gm]; slot_s[tid] = g_slot[e][gm];
        } else {
            tok_s[tid] = 0; w_s[tid] = 0.f; slot_s[tid] = 0;
        }
    }
    __syncthreads();

    // loader: 2 threads per row; each thread does 4 contiguous 16B chunks (64B)
    const int lr = tid >> 1;            // 0..127
    const int lc = (tid & 1) * 4;       // 16B-chunk base (0 or 4)
    const __half* Asrc = g_Xh + (size_t)tok_s[lr] * DIM + lc * 8;
    const __half* Bsrc = g_Wh + (size_t)e * DIM * DIM + (size_t)(n0 + lr) * DIM + lc * 8;

    const uint32_t sbase = smem_u32(smem);
    const uint32_t a_dst = sbase + lr * PITCH + lc * 16;
    const uint32_t b_dst = sbase + A_TILE + lr * PITCH + lc * 16;

    // 8 warps: 4 m-warps x 2 n-warps, warp tile 32x64
    const int wm = (wid & 3) * 32;
    const int wn = (wid >> 2) * 64;

    float acc[2][8][4];
#pragma unroll
    for (int mf = 0; mf < 2; mf++)
#pragma unroll
        for (int nf = 0; nf < 8; nf++)
#pragma unroll
            for (int j = 0; j < 4; j++) acc[mf][nf][j] = 0.f;

    const uint32_t aRowAddr = (uint32_t)((wm + (lane & 15)) * PITCH + (lane >> 4) * 16);
    const uint32_t bRowAddr = (uint32_t)((wn + (lane & 7) + ((lane >> 4) << 3)) * PITCH +
                                         ((lane >> 3) & 1) * 16);

    // prologue: stages 0..2 hold chunks 0..2
#pragma unroll
    for (int c = 0; c < NSTAGE; c++) {
        const uint32_t so = c * ST_SIZE;
        const int k0 = c * BK;
#pragma unroll
        for (int j = 0; j < 4; j++) {
            cp16(a_dst + so + j * 16, Asrc + k0 + j * 8);
            cp16(b_dst + so + j * 16, Bsrc + k0 + j * 8);
        }
        cp_commit();
    }

    int st = 0;
    for (int c = 0; c < NCH; c++) {
        cp_wait<NSTAGE - 1>();
        __syncthreads();

        const uint32_t bA = sbase + st * ST_SIZE;
        const uint32_t bB = bA + A_TILE;
#pragma unroll
        for (int ks = 0; ks < 4; ks++) {
            const uint32_t kb = ks * 32;
            uint32_t ah[2][4], bb[8][2];
#pragma unroll
            for (int mf = 0; mf < 2; mf++)
                ldsm4(ah[mf][0], ah[mf][1], ah[mf][2], ah[mf][3],
                      bA + aRowAddr + mf * 16 * PITCH + kb);
#pragma unroll
            for (int q = 0; q < 4; q++)
                ldsm4(bb[2 * q][0], bb[2 * q][1], bb[2 * q + 1][0], bb[2 * q + 1][1],
                      bB + bRowAddr + q * 16 * PITCH + kb);
#pragma unroll
            for (int mf = 0; mf < 2; mf++)
#pragma unroll
                for (int nf = 0; nf < 8; nf++)
                    mma16816(acc[mf][nf], ah[mf], bb[nf]);
        }
        __syncthreads();

        if (c + NSTAGE < NCH) {
            const uint32_t so = st * ST_SIZE;
            const int k0 = (c + NSTAGE) * BK;
#pragma unroll
            for (int j = 0; j < 4; j++) {
                cp16(a_dst + so + j * 16, Asrc + k0 + j * 8);
                cp16(b_dst + so + j * 16, Bsrc + k0 + j * 8);
            }
        }
        cp_commit();

        st = (st + 1 == NSTAGE) ? 0 : st + 1;
    }

    // ---- epilogue: bias + relu + gate weight -> g_C (coalesced STG) --------------
#pragma unroll
    for (int mf = 0; mf < 2; mf++) {
        const int lm0 = wm + mf * 16 + (lane >> 2);
        const int lm1 = lm0 + 8;
        const bool ok0 = (m0 + lm0) < Me;
        const bool ok1 = (m0 + lm1) < Me;
        const float w0 = w_s[lm0], w1 = w_s[lm1];
        float* d0 = g_C + (size_t)slot_s[lm0] * N_TOK * DIM + (size_t)tok_s[lm0] * DIM;
        float* d1 = g_C + (size_t)slot_s[lm1] * N_TOK * DIM + (size_t)tok_s[lm1] * DIM;
#pragma unroll
        for (int nf = 0; nf < 8; nf++) {
            const int col = n0 + wn + nf * 8 + (lane & 3) * 2;
            const float b0 = __ldg(&be[(size_t)e * DIM + col]);
            const float b1 = __ldg(&be[(size_t)e * DIM + col + 1]);
            if (ok0) {
                float v0 = fmaxf(acc[mf][nf][0] + b0, 0.f) * w0;
                float v1 = fmaxf(acc[mf][nf][1] + b1, 0.f) * w0;
                *(float2*)(d0 + col) = make_float2(v0, v1);
            }
            if (ok1) {
                float v2 = fmaxf(acc[mf][nf][2] + b0, 0.f) * w1;
                float v3 = fmaxf(acc[mf][nf][3] + b1, 0.f) * w1;
                *(float2*)(d1 + col) = make_float2(v2, v3);
            }
        }
    }
}

// ---- combine -------------------------------------------------------------------
__global__ void combine_kernel(float* __restrict__ out) {
    size_t i = (size_t)blockIdx.x * blockDim.x + threadIdx.x;
    const float4* c0 = (const float4*)g_C;
    const float4* c1 = (const float4*)(g_C + (size_t)N_TOK * DIM);
    if (i < (size_t)N_TOK * DIM / 4) {
        float4 a = c0[i];
        float4 b = c1[i];
        ((float4*)out)[i] = make_float4(a.x + b.x, a.y + b.y, a.z + b.z, a.w + b.w);
    }
}

// ---- launch ----------------------------------------------------------------------
extern "C" void kernel_launch(void* const* d_in, const int* in_sizes, int n_in,
                              void* d_out, int out_size) {
    const float* x  = (const float*)d_in[0];
    const float* We = (const float*)d_in[1];
    const float* be = (const float*)d_in[2];
    const float* Wg = (const float*)d_in[3];
    const float* bg = (const float*)d_in[4];
    float* out = (float*)d_out;

    cudaFuncSetAttribute(expert_gemm_mma,
                         cudaFuncAttributeMaxDynamicSharedMemorySize, SMEM_BYTES);

    __half* wh; cudaGetSymbolAddress((void**)&wh, g_Wh);
    __half* xh; cudaGetSymbolAddress((void**)&xh, g_Xh);

    reset_kernel<<<1, 32>>>();
    convert_f32_f16<<<((size_t)NEXP * DIM * DIM / 4 + 255) / 256, 256>>>(We, wh, (size_t)NEXP * DIM * DIM / 4);
    convert_f32_f16<<<((size_t)N_TOK * DIM / 4 + 255) / 256, 256>>>(x, xh, (size_t)N_TOK * DIM / 4);
    gating_kernel<<<N_TOK / 16, 256>>>(x, Wg, bg);
    expert_gemm_mma<<<dim3(DIM / BN, N_TOK / BM, NEXP), 256, SMEM_BYTES>>>(be);
    combine_kernel<<<(N_TOK * DIM / 4) / 256, 256>>>(out);
}

// round 8
// speedup vs baseline: 1.3105x; 1.3105x over previous
#include <cuda_runtime.h>
#include <cuda_fp16.h>
#include <cstdint>

#define N_TOK 8192
#define DIM   2048
#define NEXP  8

#define BM 128
#define BN 256
#define BK 64                  // fp16 K elems per chunk (128B row)
#define NCH (DIM / BK)         // 32
#define NSTAGE 4

#define PITCH 144              // 128B data + 16B pad -> conflict-free LDSM
#define A_TILE (BM * PITCH)    // 18432
#define B_TILE (BN * PITCH)    // 36864
#define ST_SIZE (A_TILE + B_TILE)        // 55296
#define OFF_TOK  (NSTAGE * ST_SIZE)      // 221184
#define OFF_WT   (OFF_TOK + 512)
#define OFF_SLOT (OFF_WT + 512)
#define SMEM_BYTES (OFF_SLOT + 512)      // 222720 (< 227KB cap), 1 CTA/SM

// ---- scratch ---------------------------------------------------------------
__device__ int   g_count[NEXP];
__device__ int   g_tok[NEXP][N_TOK];
__device__ float g_wt[NEXP][N_TOK];
__device__ int   g_slot[NEXP][N_TOK];
__device__ float g_C[2ull * N_TOK * DIM];
__device__ __align__(16) __half g_Wh[(size_t)NEXP * DIM * DIM];
__device__ __align__(16) __half g_Xh[(size_t)N_TOK * DIM];

// ---- helpers -----------------------------------------------------------------
__device__ __forceinline__ uint32_t smem_u32(const void* p) {
    return (uint32_t)__cvta_generic_to_shared(p);
}
__device__ __forceinline__ void cp16(uint32_t dst, const void* src) {
    asm volatile("cp.async.ca.shared.global [%0], [%1], 16;" :: "r"(dst), "l"(src));
}
__device__ __forceinline__ void cp_commit() {
    asm volatile("cp.async.commit_group;" ::: "memory");
}
template <int N>
__device__ __forceinline__ void cp_wait() {
    asm volatile("cp.async.wait_group %0;" :: "n"(N) : "memory");
}
__device__ __forceinline__ void ldsm4(uint32_t& r0, uint32_t& r1, uint32_t& r2,
                                      uint32_t& r3, uint32_t addr) {
    asm volatile("ldmatrix.sync.aligned.m8n8.x4.shared.b16 {%0,%1,%2,%3}, [%4];"
                 : "=r"(r0), "=r"(r1), "=r"(r2), "=r"(r3) : "r"(addr));
}
__device__ __forceinline__ void mma16816(float* c, const uint32_t* a, const uint32_t* b) {
    asm volatile(
        "mma.sync.aligned.m16n8k16.row.col.f32.f16.f16.f32 "
        "{%0,%1,%2,%3}, {%4,%5,%6,%7}, {%8,%9}, {%0,%1,%2,%3};"
        : "+f"(c[0]), "+f"(c[1]), "+f"(c[2]), "+f"(c[3])
        : "r"(a[0]), "r"(a[1]), "r"(a[2]), "r"(a[3]), "r"(b[0]), "r"(b[1]));
}

// ---- reset -----------------------------------------------------------------
__global__ void reset_kernel() {
    if (threadIdx.x < NEXP) g_count[threadIdx.x] = 0;
}

// ---- fp32 -> fp16 converter ----------------------------------------------------
__global__ void convert_f32_f16(const float* __restrict__ src,
                                __half* __restrict__ dst, size_t n4) {
    size_t i = (size_t)blockIdx.x * blockDim.x + threadIdx.x;
    if (i < n4) {
        float4 v = __ldg(((const float4*)src) + i);
        __half2 a = __floats2half2_rn(v.x, v.y);
        __half2 b = __floats2half2_rn(v.z, v.w);
        ((uint2*)dst)[i] = make_uint2(*(uint32_t*)&a, *(uint32_t*)&b);
    }
}

// ---- gating: 4 tokens per warp -------------------------------------------------
__global__ void gating_kernel(const float* __restrict__ x,
                              const float* __restrict__ Wg,
                              const float* __restrict__ bg) {
    int warp = (blockIdx.x * blockDim.x + threadIdx.x) >> 5;
    int lane = threadIdx.x & 31;
    int t0 = warp * 4;
    if (t0 >= N_TOK) return;

    const float4* xr[4];
#pragma unroll
    for (int t = 0; t < 4; t++)
        xr[t] = reinterpret_cast<const float4*>(x + (size_t)(t0 + t) * DIM);

    float acc[4][NEXP];
#pragma unroll
    for (int t = 0; t < 4; t++)
#pragma unroll
        for (int e = 0; e < NEXP; e++) acc[t][e] = 0.f;

    for (int d4 = lane; d4 < DIM / 4; d4 += 32) {
        float4 xv[4];
#pragma unroll
        for (int t = 0; t < 4; t++) xv[t] = __ldg(&xr[t][d4]);
#pragma unroll
        for (int e = 0; e < NEXP; e++) {
            float4 wv = __ldg(&reinterpret_cast<const float4*>(Wg + (size_t)e * DIM)[d4]);
#pragma unroll
            for (int t = 0; t < 4; t++)
                acc[t][e] += xv[t].x * wv.x + xv[t].y * wv.y +
                             xv[t].z * wv.z + xv[t].w * wv.w;
        }
    }
#pragma unroll
    for (int t = 0; t < 4; t++)
#pragma unroll
        for (int e = 0; e < NEXP; e++) {
#pragma unroll
            for (int off = 16; off > 0; off >>= 1)
                acc[t][e] += __shfl_xor_sync(0xffffffffu, acc[t][e], off);
        }

    if (lane == 0) {
#pragma unroll
        for (int t = 0; t < 4; t++) {
            int tok = t0 + t;
            float lg[NEXP];
            float mx = -1e30f;
#pragma unroll
            for (int e = 0; e < NEXP; e++) { lg[e] = acc[t][e] + bg[e]; mx = fmaxf(mx, lg[e]); }
            float s = 0.f;
#pragma unroll
            for (int e = 0; e < NEXP; e++) { lg[e] = expf(lg[e] - mx); s += lg[e]; }
            float inv = 1.f / s;

            int e0 = 0;
#pragma unroll
            for (int e = 1; e < NEXP; e++) if (lg[e] > lg[e0]) e0 = e;
            int e1 = (e0 == 0) ? 1 : 0;
#pragma unroll
            for (int e = 0; e < NEXP; e++) if (e != e0 && lg[e] > lg[e1]) e1 = e;

            int p0 = atomicAdd(&g_count[e0], 1);
            g_tok[e0][p0] = tok; g_wt[e0][p0] = lg[e0] * inv; g_slot[e0][p0] = 0;
            int p1 = atomicAdd(&g_count[e1], 1);
            g_tok[e1][p1] = tok; g_wt[e1][p1] = lg[e1] * inv; g_slot[e1][p1] = 1;
        }
    }
}

// ---- fp16 mma.sync expert GEMM ------------------------------------------------
// R4 ordering (issue AFTER compute), NSTAGE=4 -> cp target is a retired stage,
// so only ONE __syncthreads per chunk is needed.
__global__ __launch_bounds__(512, 1)
void expert_gemm_mma(const float* __restrict__ be) {
    extern __shared__ __align__(128) char smem[];

    const int e  = blockIdx.z;
    const int Me = g_count[e];
    const int m0 = blockIdx.y * BM;
    if (m0 >= Me) return;
    const int n0 = blockIdx.x * BN;

    const int tid  = threadIdx.x;
    const int wid  = tid >> 5;
    const int lane = tid & 31;

    int*   tok_s  = (int*)(smem + OFF_TOK);
    float* w_s    = (float*)(smem + OFF_WT);
    int*   slot_s = (int*)(smem + OFF_SLOT);

    if (tid < BM) {
        int gm = m0 + tid;
        if (gm < Me) {
            tok_s[tid] = g_tok[e][gm]; w_s[tid] = g_wt[e][gm]; slot_s[tid] = g_slot[e][gm];
        } else {
            tok_s[tid] = 0; w_s[tid] = 0.f; slot_s[tid] = 0;
        }
    }
    __syncthreads();

    const int lr = tid >> 2;        // 0..127
    const int lc = tid & 3;
    const __half* Asrc = g_Xh + (size_t)tok_s[lr] * DIM + lc * 8;
    const __half* Bbase = g_Wh + (size_t)e * DIM * DIM;
    const __half* Bsrc0 = Bbase + (size_t)(n0 + lr) * DIM + lc * 8;
    const __half* Bsrc1 = Bbase + (size_t)(n0 + 128 + lr) * DIM + lc * 8;

    const uint32_t sbase  = smem_u32(smem);
    const uint32_t a_dst  = sbase + lr * PITCH + lc * 16;
    const uint32_t b_dst0 = sbase + A_TILE + lr * PITCH + lc * 16;
    const uint32_t b_dst1 = sbase + A_TILE + (128 + lr) * PITCH + lc * 16;

    const int wm = (wid & 3) * 32;
    const int wn = (wid >> 2) * 64;

    float acc[2][8][4];
#pragma unroll
    for (int mf = 0; mf < 2; mf++)
#pragma unroll
        for (int nf = 0; nf < 8; nf++)
#pragma unroll
            for (int j = 0; j < 4; j++) acc[mf][nf][j] = 0.f;

    const uint32_t aRowAddr = (uint32_t)((wm + (lane & 15)) * PITCH + (lane >> 4) * 16);
    const uint32_t bRowAddr = (uint32_t)((wn + (lane & 7) + ((lane >> 4) << 3)) * PITCH +
                                         ((lane >> 3) & 1) * 16);

    // prologue: chunks 0..2 into stages 0..2 (3 commit groups)
#pragma unroll
    for (int c = 0; c < 3; c++) {
        const uint32_t so = c * ST_SIZE;
        const int k0 = c * BK;
        cp16(a_dst + so,       Asrc + k0);
        cp16(a_dst + so + 64,  Asrc + k0 + 32);
        cp16(b_dst0 + so,      Bsrc0 + k0);
        cp16(b_dst0 + so + 64, Bsrc0 + k0 + 32);
        cp16(b_dst1 + so,      Bsrc1 + k0);
        cp16(b_dst1 + so + 64, Bsrc1 + k0 + 32);
        cp_commit();
    }

    for (int c = 0; c < NCH; c++) {
        const int st = c & (NSTAGE - 1);
        cp_wait<2>();              // chunks c+1, c+2 may remain in flight
        __syncthreads();           // all threads' chunk-c data resident; stage (c-1)%4 retired

        const uint32_t bA = sbase + st * ST_SIZE;
        const uint32_t bB = bA + A_TILE;
#pragma unroll
        for (int ks = 0; ks < 4; ks++) {
            const uint32_t kb = ks * 32;
            uint32_t ah[2][4], bb[8][2];
#pragma unroll
            for (int mf = 0; mf < 2; mf++)
                ldsm4(ah[mf][0], ah[mf][1], ah[mf][2], ah[mf][3],
                      bA + aRowAddr + mf * 16 * PITCH + kb);
#pragma unroll
            for (int q = 0; q < 4; q++)
                ldsm4(bb[2 * q][0], bb[2 * q][1], bb[2 * q + 1][0], bb[2 * q + 1][1],
                      bB + bRowAddr + q * 16 * PITCH + kb);
#pragma unroll
            for (int mf = 0; mf < 2; mf++)
#pragma unroll
                for (int nf = 0; nf < 8; nf++)
                    mma16816(acc[mf][nf], ah[mf], bb[nf]);
        }

        // issue chunk c+3 into stage (c+3)%4 == (c-1)%4 (retired before top sync)
        if (c + 3 < NCH) {
            const uint32_t so = ((c + 3) & (NSTAGE - 1)) * ST_SIZE;
            const int k0 = (c + 3) * BK;
            cp16(a_dst + so,       Asrc + k0);
            cp16(a_dst + so + 64,  Asrc + k0 + 32);
            cp16(b_dst0 + so,      Bsrc0 + k0);
            cp16(b_dst0 + so + 64, Bsrc0 + k0 + 32);
            cp16(b_dst1 + so,      Bsrc1 + k0);
            cp16(b_dst1 + so + 64, Bsrc1 + k0 + 32);
        }
        cp_commit();               // one group per iteration keeps wait<2> exact
    }

    // ---- epilogue: bias + relu + gate weight -> g_C (coalesced STG) --------------
#pragma unroll
    for (int mf = 0; mf < 2; mf++) {
        const int lm0 = wm + mf * 16 + (lane >> 2);
        const int lm1 = lm0 + 8;
        const bool ok0 = (m0 + lm0) < Me;
        const bool ok1 = (m0 + lm1) < Me;
        const float w0 = w_s[lm0], w1 = w_s[lm1];
        float* d0 = g_C + (size_t)slot_s[lm0] * N_TOK * DIM + (size_t)tok_s[lm0] * DIM;
        float* d1 = g_C + (size_t)slot_s[lm1] * N_TOK * DIM + (size_t)tok_s[lm1] * DIM;
#pragma unroll
        for (int nf = 0; nf < 8; nf++) {
            const int col = n0 + wn + nf * 8 + (lane & 3) * 2;
            const float b0 = __ldg(&be[(size_t)e * DIM + col]);
            const float b1 = __ldg(&be[(size_t)e * DIM + col + 1]);
            if (ok0) {
                float v0 = fmaxf(acc[mf][nf][0] + b0, 0.f) * w0;
                float v1 = fmaxf(acc[mf][nf][1] + b1, 0.f) * w0;
                *(float2*)(d0 + col) = make_float2(v0, v1);
            }
            if (ok1) {
                float v2 = fmaxf(acc[mf][nf][2] + b0, 0.f) * w1;
                float v3 = fmaxf(acc[mf][nf][3] + b1, 0.f) * w1;
                *(float2*)(d1 + col) = make_float2(v2, v3);
            }
        }
    }
}

// ---- combine -------------------------------------------------------------------
__global__ void combine_kernel(float* __restrict__ out) {
    size_t i = (size_t)blockIdx.x * blockDim.x + threadIdx.x;
    const float4* c0 = (const float4*)g_C;
    const float4* c1 = (const float4*)(g_C + (size_t)N_TOK * DIM);
    if (i < (size_t)N_TOK * DIM / 4) {
        float4 a = c0[i];
        float4 b = c1[i];
        ((float4*)out)[i] = make_float4(a.x + b.x, a.y + b.y, a.z + b.z, a.w + b.w);
    }
}

// ---- launch ----------------------------------------------------------------------
extern "C" void kernel_launch(void* const* d_in, const int* in_sizes, int n_in,
                              void* d_out, int out_size) {
    const float* x  = (const float*)d_in[0];
    const float* We = (const float*)d_in[1];
    const float* be = (const float*)d_in[2];
    const float* Wg = (const float*)d_in[3];
    const float* bg = (const float*)d_in[4];
    float* out = (float*)d_out;

    cudaFuncSetAttribute(expert_gemm_mma,
                         cudaFuncAttributeMaxDynamicSharedMemorySize, SMEM_BYTES);

    __half* wh; cudaGetSymbolAddress((void**)&wh, g_Wh);
    __half* xh; cudaGetSymbolAddress((void**)&xh, g_Xh);

    reset_kernel<<<1, 32>>>();
    convert_f32_f16<<<((size_t)NEXP * DIM * DIM / 4 + 255) / 256, 256>>>(We, wh, (size_t)NEXP * DIM * DIM / 4);
    convert_f32_f16<<<((size_t)N_TOK * DIM / 4 + 255) / 256, 256>>>(x, xh, (size_t)N_TOK * DIM / 4);
    gating_kernel<<<N_TOK / 32, 256>>>(x, Wg, bg);
    expert_gemm_mma<<<dim3(DIM / BN, N_TOK / BM, NEXP), 512, SMEM_BYTES>>>(be);
    combine_kernel<<<(N_TOK * DIM / 4) / 256, 256>>>(out);
}

// round 9
// speedup vs baseline: 1.4650x; 1.1179x over previous
#include <cuda_runtime.h>
#include <cuda_fp16.h>
#include <cstdint>

#define N_TOK 8192
#define DIM   2048
#define NEXP  8

#define BM 128
#define BN 256
#define BK 64                  // fp16 K elems per chunk (128B row)
#define NCH (DIM / BK)         // 32
#define NSTAGE 3

#define PITCH 144              // 128B data + 16B pad -> conflict-free LDSM
#define A_TILE (BM * PITCH)    // 18432
#define B_TILE (BN * PITCH)    // 36864
#define ST_SIZE (A_TILE + B_TILE)        // 55296
#define OFF_TOK  (NSTAGE * ST_SIZE)      // 165888
#define OFF_WT   (OFF_TOK + 512)
#define OFF_SLOT (OFF_WT + 512)
#define SMEM_BYTES (OFF_SLOT + 512)      // 167424 -> ~60KB L1 left

// ---- scratch ---------------------------------------------------------------
__device__ int   g_count[NEXP];
__device__ int   g_tok[NEXP][N_TOK];
__device__ float g_wt[NEXP][N_TOK];
__device__ int   g_slot[NEXP][N_TOK];
__device__ float g_C[2ull * N_TOK * DIM];
__device__ __align__(16) __half g_Wh[(size_t)NEXP * DIM * DIM];
__device__ __align__(16) __half g_Xh[(size_t)N_TOK * DIM];

// ---- helpers -----------------------------------------------------------------
__device__ __forceinline__ uint32_t smem_u32(const void* p) {
    return (uint32_t)__cvta_generic_to_shared(p);
}
__device__ __forceinline__ void cp16(uint32_t dst, const void* src) {
    asm volatile("cp.async.cg.shared.global [%0], [%1], 16;" :: "r"(dst), "l"(src));
}
__device__ __forceinline__ void cp_commit() {
    asm volatile("cp.async.commit_group;" ::: "memory");
}
template <int N>
__device__ __forceinline__ void cp_wait() {
    asm volatile("cp.async.wait_group %0;" :: "n"(N) : "memory");
}
__device__ __forceinline__ void ldsm4(uint32_t& r0, uint32_t& r1, uint32_t& r2,
                                      uint32_t& r3, uint32_t addr) {
    asm volatile("ldmatrix.sync.aligned.m8n8.x4.shared.b16 {%0,%1,%2,%3}, [%4];"
                 : "=r"(r0), "=r"(r1), "=r"(r2), "=r"(r3) : "r"(addr));
}
__device__ __forceinline__ void mma16816(float* c, const uint32_t* a, const uint32_t* b) {
    asm volatile(
        "mma.sync.aligned.m16n8k16.row.col.f32.f16.f16.f32 "
        "{%0,%1,%2,%3}, {%4,%5,%6,%7}, {%8,%9}, {%0,%1,%2,%3};"
        : "+f"(c[0]), "+f"(c[1]), "+f"(c[2]), "+f"(c[3])
        : "r"(a[0]), "r"(a[1]), "r"(a[2]), "r"(a[3]), "r"(b[0]), "r"(b[1]));
}

// ---- reset -----------------------------------------------------------------
__global__ void reset_kernel() {
    if (threadIdx.x < NEXP) g_count[threadIdx.x] = 0;
}

// ---- fp32 -> fp16 converter ----------------------------------------------------
__global__ void convert_f32_f16(const float* __restrict__ src,
                                __half* __restrict__ dst, size_t n4) {
    size_t i = (size_t)blockIdx.x * blockDim.x + threadIdx.x;
    if (i < n4) {
        float4 v = __ldg(((const float4*)src) + i);
        __half2 a = __floats2half2_rn(v.x, v.y);
        __half2 b = __floats2half2_rn(v.z, v.w);
        ((uint2*)dst)[i] = make_uint2(*(uint32_t*)&a, *(uint32_t*)&b);
    }
}

// ---- gating: 2 tokens per warp (proven optimum, 36us) ---------------------------
__global__ void gating_kernel(const float* __restrict__ x,
                              const float* __restrict__ Wg,
                              const float* __restrict__ bg) {
    int warp = (blockIdx.x * blockDim.x + threadIdx.x) >> 5;
    int lane = threadIdx.x & 31;
    int t0 = warp * 2;
    if (t0 >= N_TOK) return;

    const float4* xr0 = reinterpret_cast<const float4*>(x + (size_t)t0 * DIM);
    const float4* xr1 = reinterpret_cast<const float4*>(x + (size_t)(t0 + 1) * DIM);
    float acc0[NEXP], acc1[NEXP];
#pragma unroll
    for (int e = 0; e < NEXP; e++) { acc0[e] = 0.f; acc1[e] = 0.f; }

    for (int d4 = lane; d4 < DIM / 4; d4 += 32) {
        float4 xv0 = __ldg(&xr0[d4]);
        float4 xv1 = __ldg(&xr1[d4]);
#pragma unroll
        for (int e = 0; e < NEXP; e++) {
            float4 wv = __ldg(&reinterpret_cast<const float4*>(Wg + (size_t)e * DIM)[d4]);
            acc0[e] += xv0.x * wv.x + xv0.y * wv.y + xv0.z * wv.z + xv0.w * wv.w;
            acc1[e] += xv1.x * wv.x + xv1.y * wv.y + xv1.z * wv.z + xv1.w * wv.w;
        }
    }
#pragma unroll
    for (int e = 0; e < NEXP; e++) {
#pragma unroll
        for (int off = 16; off > 0; off >>= 1) {
            acc0[e] += __shfl_xor_sync(0xffffffffu, acc0[e], off);
            acc1[e] += __shfl_xor_sync(0xffffffffu, acc1[e], off);
        }
    }

    if (lane == 0) {
#pragma unroll
        for (int t = 0; t < 2; t++) {
            float* acc = t ? acc1 : acc0;
            int tok = t0 + t;
            float lg[NEXP];
            float mx = -1e30f;
#pragma unroll
            for (int e = 0; e < NEXP; e++) { lg[e] = acc[e] + bg[e]; mx = fmaxf(mx, lg[e]); }
            float s = 0.f;
#pragma unroll
            for (int e = 0; e < NEXP; e++) { lg[e] = expf(lg[e] - mx); s += lg[e]; }
            float inv = 1.f / s;

            int e0 = 0;
#pragma unroll
            for (int e = 1; e < NEXP; e++) if (lg[e] > lg[e0]) e0 = e;
            int e1 = (e0 == 0) ? 1 : 0;
#pragma unroll
            for (int e = 0; e < NEXP; e++) if (e != e0 && lg[e] > lg[e1]) e1 = e;

            int p0 = atomicAdd(&g_count[e0], 1);
            g_tok[e0][p0] = tok; g_wt[e0][p0] = lg[e0] * inv; g_slot[e0][p0] = 0;
            int p1 = atomicAdd(&g_count[e1], 1);
            g_tok[e1][p1] = tok; g_wt[e1][p1] = lg[e1] * inv; g_slot[e1][p1] = 1;
        }
    }
}

// ---- fp16 mma.sync expert GEMM ------------------------------------------------
// R4 shape (3-stage, 166KB smem, 512 thr, BN=256, issue-after-compute) but with
// ONE barrier per chunk: prefetch distance 2 targets stage (c-1)%3, which the
// top-of-loop sync proves is retired by all warps.
__global__ __launch_bounds__(512, 1)
void expert_gemm_mma(const float* __restrict__ be) {
    extern __shared__ __align__(128) char smem[];

    const int e  = blockIdx.z;
    const int Me = g_count[e];
    const int m0 = blockIdx.y * BM;
    if (m0 >= Me) return;
    const int n0 = blockIdx.x * BN;

    const int tid  = threadIdx.x;
    const int wid  = tid >> 5;
    const int lane = tid & 31;

    int*   tok_s  = (int*)(smem + OFF_TOK);
    float* w_s    = (float*)(smem + OFF_WT);
    int*   slot_s = (int*)(smem + OFF_SLOT);

    if (tid < BM) {
        int gm = m0 + tid;
        if (gm < Me) {
            tok_s[tid] = g_tok[e][gm]; w_s[tid] = g_wt[e][gm]; slot_s[tid] = g_slot[e][gm];
        } else {
            tok_s[tid] = 0; w_s[tid] = 0.f; slot_s[tid] = 0;
        }
    }
    __syncthreads();

    const int lr = tid >> 2;        // 0..127
    const int lc = tid & 3;
    const __half* Asrc = g_Xh + (size_t)tok_s[lr] * DIM + lc * 8;
    const __half* Bbase = g_Wh + (size_t)e * DIM * DIM;
    const __half* Bsrc0 = Bbase + (size_t)(n0 + lr) * DIM + lc * 8;
    const __half* Bsrc1 = Bbase + (size_t)(n0 + 128 + lr) * DIM + lc * 8;

    const uint32_t sbase  = smem_u32(smem);
    const uint32_t a_dst  = sbase + lr * PITCH + lc * 16;
    const uint32_t b_dst0 = sbase + A_TILE + lr * PITCH + lc * 16;
    const uint32_t b_dst1 = sbase + A_TILE + (128 + lr) * PITCH + lc * 16;

    const int wm = (wid & 3) * 32;
    const int wn = (wid >> 2) * 64;

    float acc[2][8][4];
#pragma unroll
    for (int mf = 0; mf < 2; mf++)
#pragma unroll
        for (int nf = 0; nf < 8; nf++)
#pragma unroll
            for (int j = 0; j < 4; j++) acc[mf][nf][j] = 0.f;

    const uint32_t aRowAddr = (uint32_t)((wm + (lane & 15)) * PITCH + (lane >> 4) * 16);
    const uint32_t bRowAddr = (uint32_t)((wn + (lane & 7) + ((lane >> 4) << 3)) * PITCH +
                                         ((lane >> 3) & 1) * 16);

    // prologue: chunks 0,1 into stages 0,1 (2 commit groups)
#pragma unroll
    for (int c = 0; c < 2; c++) {
        const uint32_t so = c * ST_SIZE;
        const int k0 = c * BK;
        cp16(a_dst + so,       Asrc + k0);
        cp16(a_dst + so + 64,  Asrc + k0 + 32);
        cp16(b_dst0 + so,      Bsrc0 + k0);
        cp16(b_dst0 + so + 64, Bsrc0 + k0 + 32);
        cp16(b_dst1 + so,      Bsrc1 + k0);
        cp16(b_dst1 + so + 64, Bsrc1 + k0 + 32);
        cp_commit();
    }

    int st = 0;
    for (int c = 0; c < NCH; c++) {
        cp_wait<1>();              // chunk c resident (only c+1 may stay in flight)
        __syncthreads();           // all warps past compute of c-1 -> stage (c-1)%3 retired

        const uint32_t bA = sbase + st * ST_SIZE;
        const uint32_t bB = bA + A_TILE;
#pragma unroll
        for (int ks = 0; ks < 4; ks++) {
            const uint32_t kb = ks * 32;
            uint32_t ah[2][4], bb[8][2];
#pragma unroll
            for (int mf = 0; mf < 2; mf++)
                ldsm4(ah[mf][0], ah[mf][1], ah[mf][2], ah[mf][3],
                      bA + aRowAddr + mf * 16 * PITCH + kb);
#pragma unroll
            for (int q = 0; q < 4; q++)
                ldsm4(bb[2 * q][0], bb[2 * q][1], bb[2 * q + 1][0], bb[2 * q + 1][1],
                      bB + bRowAddr + q * 16 * PITCH + kb);
#pragma unroll
            for (int mf = 0; mf < 2; mf++)
#pragma unroll
                for (int nf = 0; nf < 8; nf++)
                    mma16816(acc[mf][nf], ah[mf], bb[nf]);
        }

        // issue chunk c+2 into stage (c+2)%3 == (c-1)%3 (retired before top sync)
        if (c + 2 < NCH) {
            const uint32_t so = ((c + 2) % NSTAGE) * ST_SIZE;
            const int k0 = (c + 2) * BK;
            cp16(a_dst + so,       Asrc + k0);
            cp16(a_dst + so + 64,  Asrc + k0 + 32);
            cp16(b_dst0 + so,      Bsrc0 + k0);
            cp16(b_dst0 + so + 64, Bsrc0 + k0 + 32);
            cp16(b_dst1 + so,      Bsrc1 + k0);
            cp16(b_dst1 + so + 64, Bsrc1 + k0 + 32);
        }
        cp_commit();               // exactly one group per iteration -> wait<1> exact

        st = (st + 1 == NSTAGE) ? 0 : st + 1;
    }

    // ---- epilogue: bias + relu + gate weight -> g_C (coalesced STG) --------------
#pragma unroll
    for (int mf = 0; mf < 2; mf++) {
        const int lm0 = wm + mf * 16 + (lane >> 2);
        const int lm1 = lm0 + 8;
        const bool ok0 = (m0 + lm0) < Me;
        const bool ok1 = (m0 + lm1) < Me;
        const float w0 = w_s[lm0], w1 = w_s[lm1];
        float* d0 = g_C + (size_t)slot_s[lm0] * N_TOK * DIM + (size_t)tok_s[lm0] * DIM;
        float* d1 = g_C + (size_t)slot_s[lm1] * N_TOK * DIM + (size_t)tok_s[lm1] * DIM;
#pragma unroll
        for (int nf = 0; nf < 8; nf++) {
            const int col = n0 + wn + nf * 8 + (lane & 3) * 2;
            const float b0 = __ldg(&be[(size_t)e * DIM + col]);
            const float b1 = __ldg(&be[(size_t)e * DIM + col + 1]);
            if (ok0) {
                float v0 = fmaxf(acc[mf][nf][0] + b0, 0.f) * w0;
                float v1 = fmaxf(acc[mf][nf][1] + b1, 0.f) * w0;
                *(float2*)(d0 + col) = make_float2(v0, v1);
            }
            if (ok1) {
                float v2 = fmaxf(acc[mf][nf][2] + b0, 0.f) * w1;
                float v3 = fmaxf(acc[mf][nf][3] + b1, 0.f) * w1;
                *(float2*)(d1 + col) = make_float2(v2, v3);
            }
        }
    }
}

// ---- combine -------------------------------------------------------------------
__global__ void combine_kernel(float* __restrict__ out) {
    size_t i = (size_t)blockIdx.x * blockDim.x + threadIdx.x;
    const float4* c0 = (const float4*)g_C;
    const float4* c1 = (const float4*)(g_C + (size_t)N_TOK * DIM);
    if (i < (size_t)N_TOK * DIM / 4) {
        float4 a = c0[i];
        float4 b = c1[i];
        ((float4*)out)[i] = make_float4(a.x + b.x, a.y + b.y, a.z + b.z, a.w + b.w);
    }
}

// ---- launch ----------------------------------------------------------------------
extern "C" void kernel_launch(void* const* d_in, const int* in_sizes, int n_in,
                              void* d_out, int out_size) {
    const float* x  = (const float*)d_in[0];
    const float* We = (const float*)d_in[1];
    const float* be = (const float*)d_in[2];
    const float* Wg = (const float*)d_in[3];
    const float* bg = (const float*)d_in[4];
    float* out = (float*)d_out;

    cudaFuncSetAttribute(expert_gemm_mma,
                         cudaFuncAttributeMaxDynamicSharedMemorySize, SMEM_BYTES);

    __half* wh; cudaGetSymbolAddress((void**)&wh, g_Wh);
    __half* xh; cudaGetSymbolAddress((void**)&xh, g_Xh);

    reset_kernel<<<1, 32>>>();
    convert_f32_f16<<<((size_t)NEXP * DIM * DIM / 4 + 255) / 256, 256>>>(We, wh, (size_t)NEXP * DIM * DIM / 4);
    convert_f32_f16<<<((size_t)N_TOK * DIM / 4 + 255) / 256, 256>>>(x, xh, (size_t)N_TOK * DIM / 4);
    gating_kernel<<<N_TOK / 16, 256>>>(x, Wg, bg);
    expert_gemm_mma<<<dim3(DIM / BN, N_TOK / BM, NEXP), 512, SMEM_BYTES>>>(be);
    combine_kernel<<<(N_TOK * DIM / 4) / 256, 256>>>(out);
}

// round 10
// speedup vs baseline: 1.4676x; 1.0017x over previous
#include <cuda_runtime.h>
#include <cuda_fp16.h>
#include <cstdint>

#define N_TOK 8192
#define DIM   2048
#define NEXP  8

#define BM 128
#define BN 256
#define BK 64                  // fp16 K elems per chunk (128B row)
#define NCH (DIM / BK)         // 32
#define NSTAGE 3

#define PITCH 144              // 128B data + 16B pad -> conflict-free LDSM
#define A_TILE (BM * PITCH)    // 18432
#define B_TILE (BN * PITCH)    // 36864
#define ST_SIZE (A_TILE + B_TILE)        // 55296
#define OFF_TOK  (NSTAGE * ST_SIZE)      // 165888
#define OFF_WT   (OFF_TOK + 512)
#define OFF_SLOT (OFF_WT + 512)
#define SMEM_BYTES (OFF_SLOT + 512)      // 167424 -> ~60KB L1 left

// ---- scratch ---------------------------------------------------------------
__device__ int   g_count[NEXP];
__device__ int   g_tok[NEXP][N_TOK];
__device__ float g_wt[NEXP][N_TOK];
__device__ int   g_slot[NEXP][N_TOK];
__device__ float g_C[2ull * N_TOK * DIM];
__device__ __align__(16) __half g_Wh[(size_t)NEXP * DIM * DIM];
__device__ __align__(16) __half g_Xh[(size_t)N_TOK * DIM];

// ---- helpers -----------------------------------------------------------------
__device__ __forceinline__ uint32_t smem_u32(const void* p) {
    return (uint32_t)__cvta_generic_to_shared(p);
}
__device__ __forceinline__ void cp16(uint32_t dst, const void* src) {
    asm volatile("cp.async.cg.shared.global [%0], [%1], 16;" :: "r"(dst), "l"(src));
}
__device__ __forceinline__ void cp_commit() {
    asm volatile("cp.async.commit_group;" ::: "memory");
}
template <int N>
__device__ __forceinline__ void cp_wait() {
    asm volatile("cp.async.wait_group %0;" :: "n"(N) : "memory");
}
__device__ __forceinline__ void ldsm4(uint32_t& r0, uint32_t& r1, uint32_t& r2,
                                      uint32_t& r3, uint32_t addr) {
    asm volatile("ldmatrix.sync.aligned.m8n8.x4.shared.b16 {%0,%1,%2,%3}, [%4];"
                 : "=r"(r0), "=r"(r1), "=r"(r2), "=r"(r3) : "r"(addr));
}
__device__ __forceinline__ void mma16816(float* c, const uint32_t* a, const uint32_t* b) {
    asm volatile(
        "mma.sync.aligned.m16n8k16.row.col.f32.f16.f16.f32 "
        "{%0,%1,%2,%3}, {%4,%5,%6,%7}, {%8,%9}, {%0,%1,%2,%3};"
        : "+f"(c[0]), "+f"(c[1]), "+f"(c[2]), "+f"(c[3])
        : "r"(a[0]), "r"(a[1]), "r"(a[2]), "r"(a[3]), "r"(b[0]), "r"(b[1]));
}

// ---- reset -----------------------------------------------------------------
__global__ void reset_kernel() {
    if (threadIdx.x < NEXP) g_count[threadIdx.x] = 0;
}

// ---- fp32 -> fp16 converter (W only; x fused into gating) -----------------------
__global__ void convert_f32_f16(const float* __restrict__ src,
                                __half* __restrict__ dst, size_t n4) {
    size_t i = (size_t)blockIdx.x * blockDim.x + threadIdx.x;
    if (i < n4) {
        float4 v = __ldg(((const float4*)src) + i);
        __half2 a = __floats2half2_rn(v.x, v.y);
        __half2 b = __floats2half2_rn(v.z, v.w);
        ((uint2*)dst)[i] = make_uint2(*(uint32_t*)&a, *(uint32_t*)&b);
    }
}

// ---- gating: 2 tokens per warp + fused x->fp16 conversion ------------------------
__global__ void gating_kernel(const float* __restrict__ x,
                              const float* __restrict__ Wg,
                              const float* __restrict__ bg) {
    int warp = (blockIdx.x * blockDim.x + threadIdx.x) >> 5;
    int lane = threadIdx.x & 31;
    int t0 = warp * 2;
    if (t0 >= N_TOK) return;

    const float4* xr0 = reinterpret_cast<const float4*>(x + (size_t)t0 * DIM);
    const float4* xr1 = reinterpret_cast<const float4*>(x + (size_t)(t0 + 1) * DIM);
    uint2* xh0 = reinterpret_cast<uint2*>(g_Xh + (size_t)t0 * DIM);
    uint2* xh1 = reinterpret_cast<uint2*>(g_Xh + (size_t)(t0 + 1) * DIM);

    float acc0[NEXP], acc1[NEXP];
#pragma unroll
    for (int e = 0; e < NEXP; e++) { acc0[e] = 0.f; acc1[e] = 0.f; }

    for (int d4 = lane; d4 < DIM / 4; d4 += 32) {
        float4 xv0 = __ldg(&xr0[d4]);
        float4 xv1 = __ldg(&xr1[d4]);

        // fused fp16 conversion + store (coalesced 8B/lane)
        {
            __half2 a0 = __floats2half2_rn(xv0.x, xv0.y);
            __half2 b0 = __floats2half2_rn(xv0.z, xv0.w);
            xh0[d4] = make_uint2(*(uint32_t*)&a0, *(uint32_t*)&b0);
            __half2 a1 = __floats2half2_rn(xv1.x, xv1.y);
            __half2 b1 = __floats2half2_rn(xv1.z, xv1.w);
            xh1[d4] = make_uint2(*(uint32_t*)&a1, *(uint32_t*)&b1);
        }

#pragma unroll
        for (int e = 0; e < NEXP; e++) {
            float4 wv = __ldg(&reinterpret_cast<const float4*>(Wg + (size_t)e * DIM)[d4]);
            acc0[e] += xv0.x * wv.x + xv0.y * wv.y + xv0.z * wv.z + xv0.w * wv.w;
            acc1[e] += xv1.x * wv.x + xv1.y * wv.y + xv1.z * wv.z + xv1.w * wv.w;
        }
    }
#pragma unroll
    for (int e = 0; e < NEXP; e++) {
#pragma unroll
        for (int off = 16; off > 0; off >>= 1) {
            acc0[e] += __shfl_xor_sync(0xffffffffu, acc0[e], off);
            acc1[e] += __shfl_xor_sync(0xffffffffu, acc1[e], off);
        }
    }

    if (lane == 0) {
#pragma unroll
        for (int t = 0; t < 2; t++) {
            float* acc = t ? acc1 : acc0;
            int tok = t0 + t;
            float lg[NEXP];
            float mx = -1e30f;
#pragma unroll
            for (int e = 0; e < NEXP; e++) { lg[e] = acc[e] + bg[e]; mx = fmaxf(mx, lg[e]); }
            float s = 0.f;
#pragma unroll
            for (int e = 0; e < NEXP; e++) { lg[e] = expf(lg[e] - mx); s += lg[e]; }
            float inv = 1.f / s;

            int e0 = 0;
#pragma unroll
            for (int e = 1; e < NEXP; e++) if (lg[e] > lg[e0]) e0 = e;
            int e1 = (e0 == 0) ? 1 : 0;
#pragma unroll
            for (int e = 0; e < NEXP; e++) if (e != e0 && lg[e] > lg[e1]) e1 = e;

            int p0 = atomicAdd(&g_count[e0], 1);
            g_tok[e0][p0] = tok; g_wt[e0][p0] = lg[e0] * inv; g_slot[e0][p0] = 0;
            int p1 = atomicAdd(&g_count[e1], 1);
            g_tok[e1][p1] = tok; g_wt[e1][p1] = lg[e1] * inv; g_slot[e1][p1] = 1;
        }
    }
}

// ---- fp16 mma.sync expert GEMM ------------------------------------------------
// R9 structure + fragment double-buffering: LDSM for ks+1 issued before the
// MMAs of ks, hiding the 29-cyc LDS latency behind 16 HMMAs.
__global__ __launch_bounds__(512, 1)
void expert_gemm_mma(const float* __restrict__ be) {
    extern __shared__ __align__(128) char smem[];

    const int e  = blockIdx.z;
    const int Me = g_count[e];
    const int m0 = blockIdx.y * BM;
    if (m0 >= Me) return;
    const int n0 = blockIdx.x * BN;

    const int tid  = threadIdx.x;
    const int wid  = tid >> 5;
    const int lane = tid & 31;

    int*   tok_s  = (int*)(smem + OFF_TOK);
    float* w_s    = (float*)(smem + OFF_WT);
    int*   slot_s = (int*)(smem + OFF_SLOT);

    if (tid < BM) {
        int gm = m0 + tid;
        if (gm < Me) {
            tok_s[tid] = g_tok[e][gm]; w_s[tid] = g_wt[e][gm]; slot_s[tid] = g_slot[e][gm];
        } else {
            tok_s[tid] = 0; w_s[tid] = 0.f; slot_s[tid] = 0;
        }
    }
    __syncthreads();

    const int lr = tid >> 2;        // 0..127
    const int lc = tid & 3;
    const __half* Asrc = g_Xh + (size_t)tok_s[lr] * DIM + lc * 8;
    const __half* Bbase = g_Wh + (size_t)e * DIM * DIM;
    const __half* Bsrc0 = Bbase + (size_t)(n0 + lr) * DIM + lc * 8;
    const __half* Bsrc1 = Bbase + (size_t)(n0 + 128 + lr) * DIM + lc * 8;

    const uint32_t sbase  = smem_u32(smem);
    const uint32_t a_dst  = sbase + lr * PITCH + lc * 16;
    const uint32_t b_dst0 = sbase + A_TILE + lr * PITCH + lc * 16;
    const uint32_t b_dst1 = sbase + A_TILE + (128 + lr) * PITCH + lc * 16;

    const int wm = (wid & 3) * 32;
    const int wn = (wid >> 2) * 64;

    float acc[2][8][4];
#pragma unroll
    for (int mf = 0; mf < 2; mf++)
#pragma unroll
        for (int nf = 0; nf < 8; nf++)
#pragma unroll
            for (int j = 0; j < 4; j++) acc[mf][nf][j] = 0.f;

    const uint32_t aRowAddr = (uint32_t)((wm + (lane & 15)) * PITCH + (lane >> 4) * 16);
    const uint32_t bRowAddr = (uint32_t)((wn + (lane & 7) + ((lane >> 4) << 3)) * PITCH +
                                         ((lane >> 3) & 1) * 16);

    // prologue: chunks 0,1 into stages 0,1
#pragma unroll
    for (int c = 0; c < 2; c++) {
        const uint32_t so = c * ST_SIZE;
        const int k0 = c * BK;
        cp16(a_dst + so,       Asrc + k0);
        cp16(a_dst + so + 64,  Asrc + k0 + 32);
        cp16(b_dst0 + so,      Bsrc0 + k0);
        cp16(b_dst0 + so + 64, Bsrc0 + k0 + 32);
        cp16(b_dst1 + so,      Bsrc1 + k0);
        cp16(b_dst1 + so + 64, Bsrc1 + k0 + 32);
        cp_commit();
    }

    int st = 0;
    for (int c = 0; c < NCH; c++) {
        cp_wait<1>();              // chunk c resident
        __syncthreads();           // stage (c-1)%3 retired by all warps

        const uint32_t bA = sbase + st * ST_SIZE;
        const uint32_t bB = bA + A_TILE;

        // fragment double buffer
        uint32_t ah[2][2][4], bb[2][8][2];
#pragma unroll
        for (int mf = 0; mf < 2; mf++)
            ldsm4(ah[0][mf][0], ah[0][mf][1], ah[0][mf][2], ah[0][mf][3],
                  bA + aRowAddr + mf * 16 * PITCH);
#pragma unroll
        for (int q = 0; q < 4; q++)
            ldsm4(bb[0][2 * q][0], bb[0][2 * q][1], bb[0][2 * q + 1][0], bb[0][2 * q + 1][1],
                  bB + bRowAddr + q * 16 * PITCH);

#pragma unroll
        for (int ks = 0; ks < 4; ks++) {
            const int cur = ks & 1, nxt = cur ^ 1;
            if (ks < 3) {
                const uint32_t kb = (ks + 1) * 32;
#pragma unroll
                for (int mf = 0; mf < 2; mf++)
                    ldsm4(ah[nxt][mf][0], ah[nxt][mf][1], ah[nxt][mf][2], ah[nxt][mf][3],
                          bA + aRowAddr + mf * 16 * PITCH + kb);
#pragma unroll
                for (int q = 0; q < 4; q++)
                    ldsm4(bb[nxt][2 * q][0], bb[nxt][2 * q][1],
                          bb[nxt][2 * q + 1][0], bb[nxt][2 * q + 1][1],
                          bB + bRowAddr + q * 16 * PITCH + kb);
            }
#pragma unroll
            for (int mf = 0; mf < 2; mf++)
#pragma unroll
                for (int nf = 0; nf < 8; nf++)
                    mma16816(acc[mf][nf], ah[cur][mf], bb[cur][nf]);
        }

        // issue chunk c+2 into stage (c+2)%3 == (c-1)%3
        if (c + 2 < NCH) {
            const uint32_t so = ((c + 2) % NSTAGE) * ST_SIZE;
            const int k0 = (c + 2) * BK;
            cp16(a_dst + so,       Asrc + k0);
            cp16(a_dst + so + 64,  Asrc + k0 + 32);
            cp16(b_dst0 + so,      Bsrc0 + k0);
            cp16(b_dst0 + so + 64, Bsrc0 + k0 + 32);
            cp16(b_dst1 + so,      Bsrc1 + k0);
            cp16(b_dst1 + so + 64, Bsrc1 + k0 + 32);
        }
        cp_commit();

        st = (st + 1 == NSTAGE) ? 0 : st + 1;
    }

    // ---- epilogue: bias + relu + gate weight -> g_C (coalesced STG) --------------
#pragma unroll
    for (int mf = 0; mf < 2; mf++) {
        const int lm0 = wm + mf * 16 + (lane >> 2);
        const int lm1 = lm0 + 8;
        const bool ok0 = (m0 + lm0) < Me;
        const bool ok1 = (m0 + lm1) < Me;
        const float w0 = w_s[lm0], w1 = w_s[lm1];
        float* d0 = g_C + (size_t)slot_s[lm0] * N_TOK * DIM + (size_t)tok_s[lm0] * DIM;
        float* d1 = g_C + (size_t)slot_s[lm1] * N_TOK * DIM + (size_t)tok_s[lm1] * DIM;
#pragma unroll
        for (int nf = 0; nf < 8; nf++) {
            const int col = n0 + wn + nf * 8 + (lane & 3) * 2;
            const float b0 = __ldg(&be[(size_t)e * DIM + col]);
            const float b1 = __ldg(&be[(size_t)e * DIM + col + 1]);
            if (ok0) {
                float v0 = fmaxf(acc[mf][nf][0] + b0, 0.f) * w0;
                float v1 = fmaxf(acc[mf][nf][1] + b1, 0.f) * w0;
                *(float2*)(d0 + col) = make_float2(v0, v1);
            }
            if (ok1) {
                float v2 = fmaxf(acc[mf][nf][2] + b0, 0.f) * w1;
                float v3 = fmaxf(acc[mf][nf][3] + b1, 0.f) * w1;
                *(float2*)(d1 + col) = make_float2(v2, v3);
            }
        }
    }
}

// ---- combine -------------------------------------------------------------------
__global__ void combine_kernel(float* __restrict__ out) {
    size_t i = (size_t)blockIdx.x * blockDim.x + threadIdx.x;
    const float4* c0 = (const float4*)g_C;
    const float4* c1 = (const float4*)(g_C + (size_t)N_TOK * DIM);
    if (i < (size_t)N_TOK * DIM / 4) {
        float4 a = c0[i];
        float4 b = c1[i];
        ((float4*)out)[i] = make_float4(a.x + b.x, a.y + b.y, a.z + b.z, a.w + b.w);
    }
}

// ---- launch ----------------------------------------------------------------------
extern "C" void kernel_launch(void* const* d_in, const int* in_sizes, int n_in,
                              void* d_out, int out_size) {
    const float* x  = (const float*)d_in[0];
    const float* We = (const float*)d_in[1];
    const float* be = (const float*)d_in[2];
    const float* Wg = (const float*)d_in[3];
    const float* bg = (const float*)d_in[4];
    float* out = (float*)d_out;

    cudaFuncSetAttribute(expert_gemm_mma,
                         cudaFuncAttributeMaxDynamicSharedMemorySize, SMEM_BYTES);

    __half* wh; cudaGetSymbolAddress((void**)&wh, g_Wh);

    reset_kernel<<<1, 32>>>();
    convert_f32_f16<<<((size_t)NEXP * DIM * DIM / 4 + 255) / 256, 256>>>(We, wh, (size_t)NEXP * DIM * DIM / 4);
    gating_kernel<<<N_TOK / 16, 256>>>(x, Wg, bg);   // also emits g_Xh
    expert_gemm_mma<<<dim3(DIM / BN, N_TOK / BM, NEXP), 512, SMEM_BYTES>>>(be);
    combine_kernel<<<(N_TOK * DIM / 4) / 256, 256>>>(out);
}